// round 2
// baseline (speedup 1.0000x reference)
#include <cuda_runtime.h>
#include <cuda_bf16.h>
#include <cstdint>

#define B_    16
#define S_    16
#define D_    4096
#define H_    32
#define KVH_  8
#define HD_   128
#define NREP_ 4
#define MAXS_ 4096
#define MROWS 256

__device__ float g_q  [MROWS * D_];
__device__ float g_kn [MROWS * KVH_ * HD_];
__device__ float g_vn [MROWS * KVH_ * HD_];
__device__ float g_ctx[MROWS * D_];

__device__ __forceinline__ unsigned f2tf(float x) {
    unsigned r; asm("cvt.rna.tf32.f32 %0, %1;" : "=r"(r) : "f"(x)); return r;
}
__device__ __forceinline__ void mma8(float* d, unsigned a0, unsigned a1, unsigned a2,
                                     unsigned a3, unsigned b0, unsigned b1) {
    asm volatile(
        "mma.sync.aligned.m16n8k8.row.col.f32.tf32.tf32.f32 "
        "{%0,%1,%2,%3}, {%4,%5,%6,%7}, {%8,%9}, {%0,%1,%2,%3};"
        : "+f"(d[0]), "+f"(d[1]), "+f"(d[2]), "+f"(d[3])
        : "r"(a0), "r"(a1), "r"(a2), "r"(a3), "r"(b0), "r"(b1));
}
__device__ __forceinline__ void cpa16(float* s, const float* g) {
    unsigned sa = (unsigned)__cvta_generic_to_shared(s);
    asm volatile("cp.async.cg.shared.global [%0], [%1], 16;" :: "r"(sa), "l"(g));
}
__device__ __forceinline__ void cp_commit() { asm volatile("cp.async.commit_group;"); }
template<int N> __device__ __forceinline__ void cp_wait() {
    asm volatile("cp.async.wait_group %0;" :: "n"(N));
}

// ======================= GEMM =======================
#define BM 128
#define BN 128
#define BK 32
#define AST 36
#define BST 136
#define GEMM_SMEM_BYTES ((2*BM*AST + 2*BK*BST) * 4)

__device__ __forceinline__ void gemm_load_stage(
    const float* __restrict__ A, const float* __restrict__ W,
    int Kdim, int ldw, int m0, int n0, float* As, float* Bs, int kt, int tid)
{
#pragma unroll
    for (int i = 0; i < 4; i++) {
        int idx = i * 256 + tid; int r = idx >> 3, c4 = idx & 7;
        cpa16(As + r * AST + c4 * 4, A + (long)(m0 + r) * Kdim + kt * BK + c4 * 4);
    }
#pragma unroll
    for (int i = 0; i < 4; i++) {
        int idx = i * 256 + tid; int r = idx >> 5, c4 = idx & 31;
        cpa16(Bs + r * BST + c4 * 4, W + (long)(kt * BK + r) * ldw + n0 + c4 * 4);
    }
    cp_commit();
}

__device__ void gemm_tile(const float* __restrict__ A, const float* __restrict__ W,
                          float* __restrict__ C, int Kdim, int ldw, int m0, int n0)
{
    extern __shared__ float sm[];
    float* As0 = sm;
    float* As1 = sm + BM * AST;
    float* Bs0 = sm + 2 * BM * AST;
    float* Bs1 = sm + 2 * BM * AST + BK * BST;

    int tid = threadIdx.x, lane = tid & 31, wid = tid >> 5;
    int wm = wid >> 2, wn = wid & 3;
    int gr = lane >> 2, kq = lane & 3;

    float acc[4][4][4];
#pragma unroll
    for (int mt = 0; mt < 4; mt++)
#pragma unroll
        for (int nt = 0; nt < 4; nt++)
#pragma unroll
            for (int i = 0; i < 4; i++) acc[mt][nt][i] = 0.f;

    int KT = Kdim / BK;
    gemm_load_stage(A, W, Kdim, ldw, m0, n0, As0, Bs0, 0, tid);

    for (int kt = 0; kt < KT; kt++) {
        float* Ab = (kt & 1) ? As1 : As0;
        float* Bb = (kt & 1) ? Bs1 : Bs0;
        if (kt + 1 < KT) {
            gemm_load_stage(A, W, Kdim, ldw, m0, n0,
                            (kt & 1) ? As0 : As1, (kt & 1) ? Bs0 : Bs1, kt + 1, tid);
            cp_wait<1>();
        } else {
            cp_wait<0>();
        }
        __syncthreads();
#pragma unroll
        for (int kk = 0; kk < 4; kk++) {
            unsigned af[4][4], bf[4][2];
#pragma unroll
            for (int mt = 0; mt < 4; mt++) {
                int rm = wm * 64 + mt * 16;
                const float* p0 = Ab + (rm + gr) * AST + kk * 8 + kq;
                const float* p1 = Ab + (rm + gr + 8) * AST + kk * 8 + kq;
                af[mt][0] = f2tf(p0[0]); af[mt][1] = f2tf(p1[0]);
                af[mt][2] = f2tf(p0[4]); af[mt][3] = f2tf(p1[4]);
            }
#pragma unroll
            for (int nt = 0; nt < 4; nt++) {
                int cb = wn * 32 + nt * 8 + gr;
                bf[nt][0] = f2tf(Bb[(kk * 8 + kq) * BST + cb]);
                bf[nt][1] = f2tf(Bb[(kk * 8 + kq + 4) * BST + cb]);
            }
#pragma unroll
            for (int mt = 0; mt < 4; mt++)
#pragma unroll
                for (int nt = 0; nt < 4; nt++)
                    mma8(acc[mt][nt], af[mt][0], af[mt][1], af[mt][2], af[mt][3],
                         bf[nt][0], bf[nt][1]);
        }
        __syncthreads();
    }

#pragma unroll
    for (int mt = 0; mt < 4; mt++)
#pragma unroll
        for (int nt = 0; nt < 4; nt++) {
            int row = m0 + wm * 64 + mt * 16 + gr;
            int col = n0 + wn * 32 + nt * 8 + 2 * kq;
            *(float2*)(C + (long)row * ldw + col) =
                make_float2(acc[mt][nt][0], acc[mt][nt][1]);
            *(float2*)(C + (long)(row + 8) * ldw + col) =
                make_float2(acc[mt][nt][2], acc[mt][nt][3]);
        }
}

__global__ void qkv_kernel(const float* __restrict__ x, const float* __restrict__ Wq,
                           const float* __restrict__ Wk, const float* __restrict__ Wv) {
    int y = blockIdx.y;
    const float* W; float* C; int ldw, n0;
    if (y < 32)      { W = Wq; C = g_q;  ldw = 4096; n0 = y * 128; }
    else if (y < 40) { W = Wk; C = g_kn; ldw = 1024; n0 = (y - 32) * 128; }
    else             { W = Wv; C = g_vn; ldw = 1024; n0 = (y - 40) * 128; }
    gemm_tile(x, W, C, 4096, ldw, blockIdx.x * BM, n0);
}

__global__ void out_kernel(const float* __restrict__ Wo, float* __restrict__ out) {
    gemm_tile(g_ctx, Wo, out, 4096, 4096, blockIdx.x * BM, blockIdx.y * 128);
}

// ======================= RoPE =======================
__global__ void rope_kernel(const int* __restrict__ sp) {
    int idx = blockIdx.x * blockDim.x + threadIdx.x;
    const int qpairs = MROWS * D_ / 2;
    const int kpairs = MROWS * KVH_ * HD_ / 2;
    float* base; int ppr; int i;
    if (idx < qpairs)               { base = g_q;  ppr = D_ / 2;         i = idx; }
    else if (idx < qpairs + kpairs) { base = g_kn; ppr = KVH_ * HD_ / 2; i = idx - qpairs; }
    else return;
    int row = i / ppr;
    int p   = i % ppr;
    int pp  = p & 63;
    int s   = row & 15;
    double f = (double)(sp[0] + s) * exp(-9.210340371976184 * ((double)pp / 64.0));
    double cd, sd; sincos(f, &sd, &cd);
    float c = (float)cd, sn = (float)sd;
    float2* ptr = (float2*)(base + (long)row * (ppr * 2) + 2 * p);
    float2 v = *ptr;
    *ptr = make_float2(v.x * c - v.y * sn, v.x * sn + v.y * c);
}

// ======================= attention =======================
#define TC   64
#define QST  132
#define KSTR 132
#define VSTR 136
#define PST  68
#define OFF_K0  (64*QST)
#define OFF_K1  (OFF_K0 + 64*KSTR)
#define OFF_V0  (OFF_K1 + 64*KSTR)
#define OFF_V1  (OFF_V0 + 64*VSTR)
#define OFF_P   (OFF_V1 + 64*VSTR)
#define OFF_M   (OFF_P + 64*PST)
#define OFF_L   (OFF_M + 64)
#define OFF_SC  (OFF_L + 64)
#define ATTN_SMEM_BYTES ((OFF_SC + 64) * 4)

__device__ __forceinline__ void attn_load_kv(
    const float* __restrict__ cache_k, const float* __restrict__ cache_v,
    int b, int kvh, int start, int kvlen, int t0, float* Ks, float* Vs, int tid)
{
#pragma unroll
    for (int i = 0; i < 8; i++) {
        int idx = i * 256 + tid; int r = idx >> 5, c4 = idx & 31;
        int t = t0 + r;
        if (t < start) {
            long o = ((((long)b * MAXS_ + t) * KVH_) + kvh) * HD_ + c4 * 4;
            cpa16(Ks + r * KSTR + c4 * 4, cache_k + o);
            cpa16(Vs + r * VSTR + c4 * 4, cache_v + o);
        } else if (t < kvlen) {
            long o = (((long)(b * S_ + (t - start))) * KVH_ + kvh) * HD_ + c4 * 4;
            cpa16(Ks + r * KSTR + c4 * 4, g_kn + o);
            cpa16(Vs + r * VSTR + c4 * 4, g_vn + o);
        } else {
            *(float4*)(Ks + r * KSTR + c4 * 4) = make_float4(0.f, 0.f, 0.f, 0.f);
            *(float4*)(Vs + r * VSTR + c4 * 4) = make_float4(0.f, 0.f, 0.f, 0.f);
        }
    }
    cp_commit();
}

__global__ void attn_kernel(const float* __restrict__ cache_k,
                            const float* __restrict__ cache_v,
                            const int* __restrict__ sp)
{
    extern __shared__ float sm[];
    float* Qs     = sm;
    float* Ksb[2] = { sm + OFF_K0, sm + OFF_K1 };
    float* Vsb[2] = { sm + OFF_V0, sm + OFF_V1 };
    float* Ps     = sm + OFF_P;
    float* row_m  = sm + OFF_M;
    float* row_l  = sm + OFF_L;
    float* row_sc = sm + OFF_SC;

    int tid = threadIdx.x, lane = tid & 31, wid = tid >> 5;
    int b = blockIdx.x >> 3, kvh = blockIdx.x & 7;
    int start = sp[0], kvlen = start + S_;
    int wm = wid & 3, wn = wid >> 2;
    int gr = lane >> 2, kq = lane & 3;
    int rm = wm * 16;

    const float scale = 0.08838834764831845f; // 1/sqrt(128)
#pragma unroll
    for (int i = 0; i < 8; i++) {
        int idx = i * 256 + tid; int r = idx >> 5, c4 = idx & 31;
        int rep = r >> 4, s = r & 15;
        const float4 v = *(const float4*)(g_q + (long)(b * S_ + s) * D_ +
                                          (kvh * NREP_ + rep) * HD_ + c4 * 4);
        *(float4*)(Qs + r * QST + c4 * 4) =
            make_float4(v.x * scale, v.y * scale, v.z * scale, v.w * scale);
    }
    if (tid < 64) { row_m[tid] = -1e30f; row_l[tid] = 0.f; }

    float cacc[8][4];
#pragma unroll
    for (int nt = 0; nt < 8; nt++)
#pragma unroll
        for (int i = 0; i < 4; i++) cacc[nt][i] = 0.f;

    int NCH = (kvlen + TC - 1) / TC;
    attn_load_kv(cache_k, cache_v, b, kvh, start, kvlen, 0, Ksb[0], Vsb[0], tid);

    for (int j = 0; j < NCH; j++) {
        if (j + 1 < NCH) {
            attn_load_kv(cache_k, cache_v, b, kvh, start, kvlen,
                         (j + 1) * TC, Ksb[(j + 1) & 1], Vsb[(j + 1) & 1], tid);
            cp_wait<1>();
        } else {
            cp_wait<0>();
        }
        __syncthreads();
        const float* Kb = Ksb[j & 1];
        const float* Vb = Vsb[j & 1];

        // S = Q K^T  (64 x 64)
        float sacc[4][4];
#pragma unroll
        for (int nt = 0; nt < 4; nt++)
#pragma unroll
            for (int i = 0; i < 4; i++) sacc[nt][i] = 0.f;
#pragma unroll
        for (int kk = 0; kk < 16; kk++) {
            const float* q0 = Qs + (rm + gr) * QST + kk * 8 + kq;
            const float* q1 = Qs + (rm + gr + 8) * QST + kk * 8 + kq;
            unsigned a0 = f2tf(q0[0]), a1 = f2tf(q1[0]);
            unsigned a2 = f2tf(q0[4]), a3 = f2tf(q1[4]);
#pragma unroll
            for (int nt = 0; nt < 4; nt++) {
                int cb = wn * 32 + nt * 8 + gr;
                unsigned b0 = f2tf(Kb[cb * KSTR + kk * 8 + kq]);
                unsigned b1 = f2tf(Kb[cb * KSTR + kk * 8 + kq + 4]);
                mma8(sacc[nt], a0, a1, a2, a3, b0, b1);
            }
        }
#pragma unroll
        for (int nt = 0; nt < 4; nt++) {
            int cb = wn * 32 + nt * 8 + 2 * kq;
            Ps[(rm + gr) * PST + cb]         = sacc[nt][0];
            Ps[(rm + gr) * PST + cb + 1]     = sacc[nt][1];
            Ps[(rm + gr + 8) * PST + cb]     = sacc[nt][2];
            Ps[(rm + gr + 8) * PST + cb + 1] = sacc[nt][3];
        }
        __syncthreads();

        // online softmax: 4 threads per row
        {
            int row = tid >> 2, sub = tid & 3;
            int t0c = j * TC;
            float pv[16]; float mloc = -1e30f;
#pragma unroll
            for (int c = 0; c < 16; c++) {
                int col = sub * 16 + c;
                float v = Ps[row * PST + col];
                if (t0c + col >= kvlen) v = -1e30f;
                pv[c] = v; mloc = fmaxf(mloc, v);
            }
            mloc = fmaxf(mloc, __shfl_xor_sync(0xffffffffu, mloc, 1));
            mloc = fmaxf(mloc, __shfl_xor_sync(0xffffffffu, mloc, 2));
            float mold = row_m[row];
            float mnew = fmaxf(mold, mloc);
            float lloc = 0.f;
#pragma unroll
            for (int c = 0; c < 16; c++) {
                float p = __expf(pv[c] - mnew);
                Ps[row * PST + sub * 16 + c] = p;
                lloc += p;
            }
            lloc += __shfl_xor_sync(0xffffffffu, lloc, 1);
            lloc += __shfl_xor_sync(0xffffffffu, lloc, 2);
            __syncwarp();
            if (sub == 0) {
                float scl = __expf(mold - mnew);
                row_l[row] = row_l[row] * scl + lloc;
                row_m[row] = mnew;
                row_sc[row] = scl;
            }
        }
        __syncthreads();

        // O = P V   (rescale accumulators, then accumulate)
        {
            float sc0 = row_sc[rm + gr], sc1 = row_sc[rm + gr + 8];
#pragma unroll
            for (int nt = 0; nt < 8; nt++) {
                cacc[nt][0] *= sc0; cacc[nt][1] *= sc0;
                cacc[nt][2] *= sc1; cacc[nt][3] *= sc1;
            }
#pragma unroll
            for (int kk = 0; kk < 8; kk++) {
                unsigned a0 = f2tf(Ps[(rm + gr) * PST + kk * 8 + kq]);
                unsigned a1 = f2tf(Ps[(rm + gr + 8) * PST + kk * 8 + kq]);
                unsigned a2 = f2tf(Ps[(rm + gr) * PST + kk * 8 + kq + 4]);
                unsigned a3 = f2tf(Ps[(rm + gr + 8) * PST + kk * 8 + kq + 4]);
#pragma unroll
                for (int nt = 0; nt < 8; nt++) {
                    int dc = wn * 64 + nt * 8 + gr;
                    unsigned b0 = f2tf(Vb[(kk * 8 + kq) * VSTR + dc]);
                    unsigned b1 = f2tf(Vb[(kk * 8 + kq + 4) * VSTR + dc]);
                    mma8(cacc[nt], a0, a1, a2, a3, b0, b1);
                }
            }
        }
        __syncthreads();
    }

    // epilogue: normalize, write ctx
    float inv0 = 1.f / row_l[rm + gr];
    float inv1 = 1.f / row_l[rm + gr + 8];
    int r0 = rm + gr, r1 = rm + gr + 8;
    long base0 = (long)(b * S_ + (r0 & 15)) * D_ + (kvh * NREP_ + (r0 >> 4)) * HD_;
    long base1 = (long)(b * S_ + (r1 & 15)) * D_ + (kvh * NREP_ + (r1 >> 4)) * HD_;
#pragma unroll
    for (int nt = 0; nt < 8; nt++) {
        int col = wn * 64 + nt * 8 + 2 * kq;
        *(float2*)(g_ctx + base0 + col) = make_float2(cacc[nt][0] * inv0, cacc[nt][1] * inv0);
        *(float2*)(g_ctx + base1 + col) = make_float2(cacc[nt][2] * inv1, cacc[nt][3] * inv1);
    }
}

// ======================= launch =======================
extern "C" void kernel_launch(void* const* d_in, const int* in_sizes, int n_in,
                              void* d_out, int out_size) {
    const float* x       = (const float*)d_in[0];
    const float* Wq      = (const float*)d_in[1];
    const float* Wk      = (const float*)d_in[2];
    const float* Wv      = (const float*)d_in[3];
    const float* Wo      = (const float*)d_in[4];
    const float* cache_k = (const float*)d_in[5];
    const float* cache_v = (const float*)d_in[6];
    const int*   sp      = (const int*)d_in[7];
    float* out = (float*)d_out;

    cudaFuncSetAttribute(qkv_kernel, cudaFuncAttributeMaxDynamicSharedMemorySize, GEMM_SMEM_BYTES);
    cudaFuncSetAttribute(out_kernel, cudaFuncAttributeMaxDynamicSharedMemorySize, GEMM_SMEM_BYTES);
    cudaFuncSetAttribute(attn_kernel, cudaFuncAttributeMaxDynamicSharedMemorySize, ATTN_SMEM_BYTES);

    qkv_kernel<<<dim3(2, 48), 256, GEMM_SMEM_BYTES>>>(x, Wq, Wk, Wv);
    rope_kernel<<<2560, 256>>>(sp);
    attn_kernel<<<128, 256, ATTN_SMEM_BYTES>>>(cache_k, cache_v, sp);
    out_kernel<<<dim3(2, 32), 256, GEMM_SMEM_BYTES>>>(Wo, out);
}

// round 3
// speedup vs baseline: 1.2534x; 1.2534x over previous
#include <cuda_runtime.h>
#include <cuda_bf16.h>
#include <cstdint>

#define B_    16
#define S_    16
#define D_    4096
#define H_    32
#define KVH_  8
#define HD_   128
#define NREP_ 4
#define MAXS_ 4096
#define MROWS 256

__device__ float  g_q  [MROWS * D_];
__device__ float  g_kn [MROWS * KVH_ * HD_];
__device__ float  g_vn [MROWS * KVH_ * HD_];
__device__ float  g_ctx[MROWS * D_];
__device__ float2 g_tab[S_ * 64];          // rope cos/sin table [s][pp]

__device__ __forceinline__ unsigned f2tf(float x) {
    unsigned r; asm("cvt.rna.tf32.f32 %0, %1;" : "=r"(r) : "f"(x)); return r;
}
__device__ __forceinline__ void mma8(float* d, unsigned a0, unsigned a1, unsigned a2,
                                     unsigned a3, unsigned b0, unsigned b1) {
    asm volatile(
        "mma.sync.aligned.m16n8k8.row.col.f32.tf32.tf32.f32 "
        "{%0,%1,%2,%3}, {%4,%5,%6,%7}, {%8,%9}, {%0,%1,%2,%3};"
        : "+f"(d[0]), "+f"(d[1]), "+f"(d[2]), "+f"(d[3])
        : "r"(a0), "r"(a1), "r"(a2), "r"(a3), "r"(b0), "r"(b1));
}
__device__ __forceinline__ void cpa16(float* s, const float* g) {
    unsigned sa = (unsigned)__cvta_generic_to_shared(s);
    asm volatile("cp.async.cg.shared.global [%0], [%1], 16;" :: "r"(sa), "l"(g));
}
__device__ __forceinline__ void cp_commit() { asm volatile("cp.async.commit_group;"); }
template<int N> __device__ __forceinline__ void cp_wait() {
    asm volatile("cp.async.wait_group %0;" :: "n"(N));
}
#define PAIR_BAR(id) asm volatile("bar.sync %0, 64;" :: "r"(id) : "memory")

// ======================= rope table =======================
__global__ void rope_tab_kernel(const int* __restrict__ sp) {
    int idx = threadIdx.x;            // 1024 threads: s(4b) x pp(6b)
    int s = idx >> 6, pp = idx & 63;
    double f = (double)(sp[0] + s) * exp(-9.210340371976184 * ((double)pp / 64.0));
    double cd, sd; sincos(f, &sd, &cd);
    g_tab[idx] = make_float2((float)cd, (float)sd);
}

// ======================= GEMM 128x128 (qkv, with fused rope epilogue) =======================
#define BM 128
#define BK 32
#define AST 36
#define BST 136
#define GEMM_SMEM_BYTES ((2*BM*AST + 2*BK*BST) * 4)

__device__ __forceinline__ void gemm_load_stage(
    const float* __restrict__ A, const float* __restrict__ W,
    int Kdim, int ldw, int m0, int n0, float* As, float* Bs, int kt, int tid)
{
#pragma unroll
    for (int i = 0; i < 4; i++) {
        int idx = i * 256 + tid; int r = idx >> 3, c4 = idx & 7;
        cpa16(As + r * AST + c4 * 4, A + (long)(m0 + r) * Kdim + kt * BK + c4 * 4);
    }
#pragma unroll
    for (int i = 0; i < 4; i++) {
        int idx = i * 256 + tid; int r = idx >> 5, c4 = idx & 31;
        cpa16(Bs + r * BST + c4 * 4, W + (long)(kt * BK + r) * ldw + n0 + c4 * 4);
    }
    cp_commit();
}

// mode: 0 plain, 1 rope (K), 2 rope+qscale (Q)
__device__ void gemm_tile(const float* __restrict__ A, const float* __restrict__ W,
                          float* __restrict__ C, int Kdim, int ldw, int m0, int n0, int mode)
{
    extern __shared__ float sm[];
    float* As0 = sm;
    float* As1 = sm + BM * AST;
    float* Bs0 = sm + 2 * BM * AST;
    float* Bs1 = sm + 2 * BM * AST + BK * BST;

    int tid = threadIdx.x, lane = tid & 31, wid = tid >> 5;
    int wm = wid >> 2, wn = wid & 3;
    int gr = lane >> 2, kq = lane & 3;

    float acc[4][4][4];
#pragma unroll
    for (int mt = 0; mt < 4; mt++)
#pragma unroll
        for (int nt = 0; nt < 4; nt++)
#pragma unroll
            for (int i = 0; i < 4; i++) acc[mt][nt][i] = 0.f;

    int KT = Kdim / BK;
    gemm_load_stage(A, W, Kdim, ldw, m0, n0, As0, Bs0, 0, tid);

    for (int kt = 0; kt < KT; kt++) {
        float* Ab = (kt & 1) ? As1 : As0;
        float* Bb = (kt & 1) ? Bs1 : Bs0;
        if (kt + 1 < KT) {
            gemm_load_stage(A, W, Kdim, ldw, m0, n0,
                            (kt & 1) ? As0 : As1, (kt & 1) ? Bs0 : Bs1, kt + 1, tid);
            cp_wait<1>();
        } else {
            cp_wait<0>();
        }
        __syncthreads();
#pragma unroll
        for (int kk = 0; kk < 4; kk++) {
            unsigned af[4][4], bf[4][2];
#pragma unroll
            for (int mt = 0; mt < 4; mt++) {
                int rm = wm * 64 + mt * 16;
                const float* p0 = Ab + (rm + gr) * AST + kk * 8 + kq;
                const float* p1 = Ab + (rm + gr + 8) * AST + kk * 8 + kq;
                af[mt][0] = f2tf(p0[0]); af[mt][1] = f2tf(p1[0]);
                af[mt][2] = f2tf(p0[4]); af[mt][3] = f2tf(p1[4]);
            }
#pragma unroll
            for (int nt = 0; nt < 4; nt++) {
                int cb = wn * 32 + nt * 8 + gr;
                bf[nt][0] = f2tf(Bb[(kk * 8 + kq) * BST + cb]);
                bf[nt][1] = f2tf(Bb[(kk * 8 + kq + 4) * BST + cb]);
            }
#pragma unroll
            for (int mt = 0; mt < 4; mt++)
#pragma unroll
                for (int nt = 0; nt < 4; nt++)
                    mma8(acc[mt][nt], af[mt][0], af[mt][1], af[mt][2], af[mt][3],
                         bf[nt][0], bf[nt][1]);
        }
        __syncthreads();
    }

    float qs = (mode == 2) ? 0.08838834764831845f : 1.f;
#pragma unroll
    for (int mt = 0; mt < 4; mt++)
#pragma unroll
        for (int nt = 0; nt < 4; nt++) {
            int row = m0 + wm * 64 + mt * 16 + gr;
            int col = n0 + wn * 32 + nt * 8 + 2 * kq;
            float x0 = acc[mt][nt][0], x1 = acc[mt][nt][1];
            float y0 = acc[mt][nt][2], y1 = acc[mt][nt][3];
            if (mode) {
                int pp = (col & 127) >> 1;
                float2 c0 = g_tab[((row & 15) << 6) + pp];
                float2 c1 = g_tab[(((row + 8) & 15) << 6) + pp];
                float t0 = (x0 * c0.x - x1 * c0.y) * qs;
                x1 = (x0 * c0.y + x1 * c0.x) * qs; x0 = t0;
                float t1 = (y0 * c1.x - y1 * c1.y) * qs;
                y1 = (y0 * c1.y + y1 * c1.x) * qs; y0 = t1;
            }
            *(float2*)(C + (long)row * ldw + col) = make_float2(x0, x1);
            *(float2*)(C + (long)(row + 8) * ldw + col) = make_float2(y0, y1);
        }
}

__global__ void qkv_kernel(const float* __restrict__ x, const float* __restrict__ Wq,
                           const float* __restrict__ Wk, const float* __restrict__ Wv) {
    int y = blockIdx.y;
    const float* W; float* C; int ldw, n0, mode;
    if (y < 32)      { W = Wq; C = g_q;  ldw = 4096; n0 = y * 128;        mode = 2; }
    else if (y < 40) { W = Wk; C = g_kn; ldw = 1024; n0 = (y - 32) * 128; mode = 1; }
    else             { W = Wv; C = g_vn; ldw = 1024; n0 = (y - 40) * 128; mode = 0; }
    gemm_tile(x, W, C, 4096, ldw, blockIdx.x * BM, n0, mode);
}

// ======================= GEMM 64x128 (out projection) =======================
#define BM64 64
#define GEMM64_SMEM_BYTES ((2*BM64*AST + 2*BK*BST) * 4)

__global__ void out_kernel(const float* __restrict__ Wo, float* __restrict__ out) {
    extern __shared__ float sm[];
    float* As0 = sm;
    float* As1 = sm + BM64 * AST;
    float* Bs0 = sm + 2 * BM64 * AST;
    float* Bs1 = sm + 2 * BM64 * AST + BK * BST;

    const float* A = g_ctx;
    int m0 = blockIdx.x * BM64, n0 = blockIdx.y * 128;
    int tid = threadIdx.x, lane = tid & 31, wid = tid >> 5;
    int wm = wid >> 2, wn = wid & 3;     // 2 x 4 warps, warp tile 32x32
    int gr = lane >> 2, kq = lane & 3;

    float acc[2][4][4];
#pragma unroll
    for (int mt = 0; mt < 2; mt++)
#pragma unroll
        for (int nt = 0; nt < 4; nt++)
#pragma unroll
            for (int i = 0; i < 4; i++) acc[mt][nt][i] = 0.f;

    const int KT = 4096 / BK;
    // stage 0
    {
#pragma unroll
        for (int i = 0; i < 2; i++) {
            int idx = i * 256 + tid; int r = idx >> 3, c4 = idx & 7;
            cpa16(As0 + r * AST + c4 * 4, A + (long)(m0 + r) * 4096 + c4 * 4);
        }
#pragma unroll
        for (int i = 0; i < 4; i++) {
            int idx = i * 256 + tid; int r = idx >> 5, c4 = idx & 31;
            cpa16(Bs0 + r * BST + c4 * 4, Wo + (long)r * 4096 + n0 + c4 * 4);
        }
        cp_commit();
    }

    for (int kt = 0; kt < KT; kt++) {
        float* Ab = (kt & 1) ? As1 : As0;
        float* Bb = (kt & 1) ? Bs1 : Bs0;
        if (kt + 1 < KT) {
            float* An = (kt & 1) ? As0 : As1;
            float* Bn = (kt & 1) ? Bs0 : Bs1;
#pragma unroll
            for (int i = 0; i < 2; i++) {
                int idx = i * 256 + tid; int r = idx >> 3, c4 = idx & 7;
                cpa16(An + r * AST + c4 * 4, A + (long)(m0 + r) * 4096 + (kt + 1) * BK + c4 * 4);
            }
#pragma unroll
            for (int i = 0; i < 4; i++) {
                int idx = i * 256 + tid; int r = idx >> 5, c4 = idx & 31;
                cpa16(Bn + r * BST + c4 * 4, Wo + (long)((kt + 1) * BK + r) * 4096 + n0 + c4 * 4);
            }
            cp_commit();
            cp_wait<1>();
        } else {
            cp_wait<0>();
        }
        __syncthreads();
#pragma unroll
        for (int kk = 0; kk < 4; kk++) {
            unsigned af[2][4], bf[4][2];
#pragma unroll
            for (int mt = 0; mt < 2; mt++) {
                int rm = wm * 32 + mt * 16;
                const float* p0 = Ab + (rm + gr) * AST + kk * 8 + kq;
                const float* p1 = Ab + (rm + gr + 8) * AST + kk * 8 + kq;
                af[mt][0] = f2tf(p0[0]); af[mt][1] = f2tf(p1[0]);
                af[mt][2] = f2tf(p0[4]); af[mt][3] = f2tf(p1[4]);
            }
#pragma unroll
            for (int nt = 0; nt < 4; nt++) {
                int cb = wn * 32 + nt * 8 + gr;
                bf[nt][0] = f2tf(Bb[(kk * 8 + kq) * BST + cb]);
                bf[nt][1] = f2tf(Bb[(kk * 8 + kq + 4) * BST + cb]);
            }
#pragma unroll
            for (int mt = 0; mt < 2; mt++)
#pragma unroll
                for (int nt = 0; nt < 4; nt++)
                    mma8(acc[mt][nt], af[mt][0], af[mt][1], af[mt][2], af[mt][3],
                         bf[nt][0], bf[nt][1]);
        }
        __syncthreads();
    }

#pragma unroll
    for (int mt = 0; mt < 2; mt++)
#pragma unroll
        for (int nt = 0; nt < 4; nt++) {
            int row = m0 + wm * 32 + mt * 16 + gr;
            int col = n0 + wn * 32 + nt * 8 + 2 * kq;
            *(float2*)(out + (long)row * 4096 + col) =
                make_float2(acc[mt][nt][0], acc[mt][nt][1]);
            *(float2*)(out + (long)(row + 8) * 4096 + col) =
                make_float2(acc[mt][nt][2], acc[mt][nt][3]);
        }
}

// ======================= attention =======================
#define TC   64
#define KSTR 132
#define VSTR 136
#define PST  68
#define AOFF_K0  0
#define AOFF_K1  (64*KSTR)
#define AOFF_V0  (2*64*KSTR)
#define AOFF_V1  (AOFF_V0 + 64*VSTR)
#define AOFF_P   (AOFF_V1 + 64*VSTR)
#define AOFF_EX  (AOFF_P + 64*PST)
#define ATTN_SMEM_BYTES ((AOFF_EX + 256) * 4)

__device__ __forceinline__ void attn_load_kv(
    const float* __restrict__ cache_k, const float* __restrict__ cache_v,
    int b, int kvh, int start, int kvlen, int t0, float* Ks, float* Vs, int tid)
{
#pragma unroll
    for (int i = 0; i < 8; i++) {
        int idx = i * 256 + tid; int r = idx >> 5, c4 = idx & 31;
        int t = t0 + r;
        if (t < start) {
            long o = ((((long)b * MAXS_ + t) * KVH_) + kvh) * HD_ + c4 * 4;
            cpa16(Ks + r * KSTR + c4 * 4, cache_k + o);
            cpa16(Vs + r * VSTR + c4 * 4, cache_v + o);
        } else if (t < kvlen) {
            long o = (((long)(b * S_ + (t - start))) * KVH_ + kvh) * HD_ + c4 * 4;
            cpa16(Ks + r * KSTR + c4 * 4, g_kn + o);
            cpa16(Vs + r * VSTR + c4 * 4, g_vn + o);
        } else {
            *(float4*)(Ks + r * KSTR + c4 * 4) = make_float4(0.f, 0.f, 0.f, 0.f);
            *(float4*)(Vs + r * VSTR + c4 * 4) = make_float4(0.f, 0.f, 0.f, 0.f);
        }
    }
    cp_commit();
}

__global__ void __launch_bounds__(256, 1)
attn_kernel(const float* __restrict__ cache_k,
            const float* __restrict__ cache_v,
            const int* __restrict__ sp)
{
    extern __shared__ float sm[];
    float* Ksb[2] = { sm + AOFF_K0, sm + AOFF_K1 };
    float* Vsb[2] = { sm + AOFF_V0, sm + AOFF_V1 };
    float* Ps = sm + AOFF_P;
    float* ex = sm + AOFF_EX;  // [0:128) m partials, [128:256) l partials

    int tid = threadIdx.x, lane = tid & 31, wid = tid >> 5;
    int b = blockIdx.x >> 3, kvh = blockIdx.x & 7;
    int start = sp[0], kvlen = start + S_;
    int wm = wid & 3, wn = wid >> 2;        // pair partner: wid ^ 4
    int gr = lane >> 2, kq = lane & 3;
    int rm = wm * 16;

    // ---- hoist Q fragments into registers (reused by all chunks) ----
    unsigned qa[16][4];
    {
        int r0 = rm + gr, r1 = r0 + 8;
        const float* q0 = g_q + (long)(b * S_ + (r0 & 15)) * D_ + (kvh * NREP_ + (r0 >> 4)) * HD_;
        const float* q1 = g_q + (long)(b * S_ + (r1 & 15)) * D_ + (kvh * NREP_ + (r1 >> 4)) * HD_;
#pragma unroll
        for (int kk = 0; kk < 16; kk++) {
            qa[kk][0] = f2tf(q0[kk * 8 + kq]);
            qa[kk][1] = f2tf(q1[kk * 8 + kq]);
            qa[kk][2] = f2tf(q0[kk * 8 + kq + 4]);
            qa[kk][3] = f2tf(q1[kk * 8 + kq + 4]);
        }
    }

    float m0r = -1e30f, m1r = -1e30f, l0r = 0.f, l1r = 0.f;
    float cacc[8][4];
#pragma unroll
    for (int nt = 0; nt < 8; nt++)
#pragma unroll
        for (int i = 0; i < 4; i++) cacc[nt][i] = 0.f;

    int NCH = (kvlen + TC - 1) / TC;
    attn_load_kv(cache_k, cache_v, b, kvh, start, kvlen, 0, Ksb[0], Vsb[0], tid);
    attn_load_kv(cache_k, cache_v, b, kvh, start, kvlen, TC, Ksb[1], Vsb[1], tid);
    cp_wait<1>();
    __syncthreads();

    for (int j = 0; j < NCH; j++) {
        const float* Kb = Ksb[j & 1];
        const float* Vb = Vsb[j & 1];

        // ---- S = Q K^T ----
        float sacc[4][4];
#pragma unroll
        for (int nt = 0; nt < 4; nt++)
#pragma unroll
            for (int i = 0; i < 4; i++) sacc[nt][i] = 0.f;
#pragma unroll
        for (int kk = 0; kk < 16; kk++) {
#pragma unroll
            for (int nt = 0; nt < 4; nt++) {
                int cb = wn * 32 + nt * 8 + gr;
                unsigned b0 = f2tf(Kb[cb * KSTR + kk * 8 + kq]);
                unsigned b1 = f2tf(Kb[cb * KSTR + kk * 8 + kq + 4]);
                mma8(sacc[nt], qa[kk][0], qa[kk][1], qa[kk][2], qa[kk][3], b0, b1);
            }
        }

        // ---- tail mask (not taken when kvlen % 64 == 0) ----
        if (j == NCH - 1 && (kvlen & (TC - 1))) {
#pragma unroll
            for (int nt = 0; nt < 4; nt++) {
                int cb = j * TC + wn * 32 + nt * 8 + 2 * kq;
                if (cb >= kvlen)     { sacc[nt][0] = -1e30f; sacc[nt][2] = -1e30f; }
                if (cb + 1 >= kvlen) { sacc[nt][1] = -1e30f; sacc[nt][3] = -1e30f; }
            }
        }

        // ---- register online softmax ----
        float mw0 = -1e30f, mw1 = -1e30f;
#pragma unroll
        for (int nt = 0; nt < 4; nt++) {
            mw0 = fmaxf(mw0, fmaxf(sacc[nt][0], sacc[nt][1]));
            mw1 = fmaxf(mw1, fmaxf(sacc[nt][2], sacc[nt][3]));
        }
        mw0 = fmaxf(mw0, __shfl_xor_sync(0xffffffffu, mw0, 1));
        mw0 = fmaxf(mw0, __shfl_xor_sync(0xffffffffu, mw0, 2));
        mw1 = fmaxf(mw1, __shfl_xor_sync(0xffffffffu, mw1, 1));
        mw1 = fmaxf(mw1, __shfl_xor_sync(0xffffffffu, mw1, 2));
        if (kq == 0) { ex[wn * 64 + rm + gr] = mw0; ex[wn * 64 + rm + gr + 8] = mw1; }
        PAIR_BAR(1 + wm);
        float M0 = fmaxf(fmaxf(mw0, ex[(1 - wn) * 64 + rm + gr]), m0r);
        float M1 = fmaxf(fmaxf(mw1, ex[(1 - wn) * 64 + rm + gr + 8]), m1r);

        float l0l = 0.f, l1l = 0.f;
#pragma unroll
        for (int nt = 0; nt < 4; nt++) {
            sacc[nt][0] = __expf(sacc[nt][0] - M0);
            sacc[nt][1] = __expf(sacc[nt][1] - M0);
            sacc[nt][2] = __expf(sacc[nt][2] - M1);
            sacc[nt][3] = __expf(sacc[nt][3] - M1);
            l0l += sacc[nt][0] + sacc[nt][1];
            l1l += sacc[nt][2] + sacc[nt][3];
        }
        l0l += __shfl_xor_sync(0xffffffffu, l0l, 1);
        l0l += __shfl_xor_sync(0xffffffffu, l0l, 2);
        l1l += __shfl_xor_sync(0xffffffffu, l1l, 1);
        l1l += __shfl_xor_sync(0xffffffffu, l1l, 2);
        if (kq == 0) { ex[128 + wn * 64 + rm + gr] = l0l; ex[128 + wn * 64 + rm + gr + 8] = l1l; }
        PAIR_BAR(1 + wm);
        float L0 = l0l + ex[128 + (1 - wn) * 64 + rm + gr];
        float L1 = l1l + ex[128 + (1 - wn) * 64 + rm + gr + 8];

        float sc0 = __expf(m0r - M0), sc1 = __expf(m1r - M1);
        l0r = l0r * sc0 + L0;  l1r = l1r * sc1 + L1;
        m0r = M0;  m1r = M1;
#pragma unroll
        for (int nt = 0; nt < 8; nt++) {
            cacc[nt][0] *= sc0; cacc[nt][1] *= sc0;
            cacc[nt][2] *= sc1; cacc[nt][3] *= sc1;
        }

        // ---- store P (pre-converted to tf32 bits) ----
#pragma unroll
        for (int nt = 0; nt < 4; nt++) {
            int cb = wn * 32 + nt * 8 + 2 * kq;
            *(float2*)&Ps[(rm + gr) * PST + cb] =
                make_float2(__uint_as_float(f2tf(sacc[nt][0])),
                            __uint_as_float(f2tf(sacc[nt][1])));
            *(float2*)&Ps[(rm + gr + 8) * PST + cb] =
                make_float2(__uint_as_float(f2tf(sacc[nt][2])),
                            __uint_as_float(f2tf(sacc[nt][3])));
        }
        __syncthreads();   // A: P visible everywhere; all K(j) reads finished

        // ---- O += P V ----
#pragma unroll
        for (int kk = 0; kk < 8; kk++) {
            unsigned a0 = __float_as_uint(Ps[(rm + gr) * PST + kk * 8 + kq]);
            unsigned a1 = __float_as_uint(Ps[(rm + gr + 8) * PST + kk * 8 + kq]);
            unsigned a2 = __float_as_uint(Ps[(rm + gr) * PST + kk * 8 + kq + 4]);
            unsigned a3 = __float_as_uint(Ps[(rm + gr + 8) * PST + kk * 8 + kq + 4]);
#pragma unroll
            for (int nt = 0; nt < 8; nt++) {
                int dc = wn * 64 + nt * 8 + gr;
                unsigned b0 = f2tf(Vb[(kk * 8 + kq) * VSTR + dc]);
                unsigned b1 = f2tf(Vb[(kk * 8 + kq + 4) * VSTR + dc]);
                mma8(cacc[nt], a0, a1, a2, a3, b0, b1);
            }
        }

        cp_wait<0>();      // chunk j+1 data resident
        __syncthreads();   // B: PV(j) done on all warps; j+1 visible
        if (j + 2 < NCH)   // refill the buffer chunk j just vacated
            attn_load_kv(cache_k, cache_v, b, kvh, start, kvlen,
                         (j + 2) * TC, Ksb[j & 1], Vsb[j & 1], tid);
    }

    // ---- epilogue ----
    float inv0 = 1.f / l0r, inv1 = 1.f / l1r;
    int r0 = rm + gr, r1 = r0 + 8;
    long base0 = (long)(b * S_ + (r0 & 15)) * D_ + (kvh * NREP_ + (r0 >> 4)) * HD_;
    long base1 = (long)(b * S_ + (r1 & 15)) * D_ + (kvh * NREP_ + (r1 >> 4)) * HD_;
#pragma unroll
    for (int nt = 0; nt < 8; nt++) {
        int col = wn * 64 + nt * 8 + 2 * kq;
        *(float2*)(g_ctx + base0 + col) = make_float2(cacc[nt][0] * inv0, cacc[nt][1] * inv0);
        *(float2*)(g_ctx + base1 + col) = make_float2(cacc[nt][2] * inv1, cacc[nt][3] * inv1);
    }
}

// ======================= launch =======================
extern "C" void kernel_launch(void* const* d_in, const int* in_sizes, int n_in,
                              void* d_out, int out_size) {
    const float* x       = (const float*)d_in[0];
    const float* Wq      = (const float*)d_in[1];
    const float* Wk      = (const float*)d_in[2];
    const float* Wv      = (const float*)d_in[3];
    const float* Wo      = (const float*)d_in[4];
    const float* cache_k = (const float*)d_in[5];
    const float* cache_v = (const float*)d_in[6];
    const int*   sp      = (const int*)d_in[7];
    float* out = (float*)d_out;

    cudaFuncSetAttribute(qkv_kernel,  cudaFuncAttributeMaxDynamicSharedMemorySize, GEMM_SMEM_BYTES);
    cudaFuncSetAttribute(out_kernel,  cudaFuncAttributeMaxDynamicSharedMemorySize, GEMM64_SMEM_BYTES);
    cudaFuncSetAttribute(attn_kernel, cudaFuncAttributeMaxDynamicSharedMemorySize, ATTN_SMEM_BYTES);

    rope_tab_kernel<<<1, 1024>>>(sp);
    qkv_kernel<<<dim3(2, 48), 256, GEMM_SMEM_BYTES>>>(x, Wq, Wk, Wv);
    attn_kernel<<<128, 256, ATTN_SMEM_BYTES>>>(cache_k, cache_v, sp);
    out_kernel<<<dim3(4, 32), 256, GEMM64_SMEM_BYTES>>>(Wo, out);
}

// round 4
// speedup vs baseline: 1.3184x; 1.0519x over previous
#include <cuda_runtime.h>
#include <cuda_bf16.h>
#include <cstdint>

#define B_    16
#define S_    16
#define D_    4096
#define H_    32
#define KVH_  8
#define HD_   128
#define NREP_ 4
#define MAXS_ 4096
#define MROWS 256
#define KS    4        // K-split factor for projection GEMMs
#define NC    6144     // qkv unified output columns (4096 q + 1024 k + 1024 v)

__device__ float  g_q  [MROWS * D_];
__device__ float  g_kn [MROWS * KVH_ * HD_];
__device__ float  g_vn [MROWS * KVH_ * HD_];
__device__ float  g_ctx[MROWS * D_];
__device__ float  g_p  [KS][MROWS * NC];   // GEMM partials (qkv, then reused by out)
__device__ float2 g_tab[S_ * 64];          // rope cos/sin [s][pp]

__device__ __forceinline__ unsigned f2tf(float x) {
    unsigned r; asm("cvt.rna.tf32.f32 %0, %1;" : "=r"(r) : "f"(x)); return r;
}
__device__ __forceinline__ void mma8(float* d, unsigned a0, unsigned a1, unsigned a2,
                                     unsigned a3, unsigned b0, unsigned b1) {
    asm volatile(
        "mma.sync.aligned.m16n8k8.row.col.f32.tf32.tf32.f32 "
        "{%0,%1,%2,%3}, {%4,%5,%6,%7}, {%8,%9}, {%0,%1,%2,%3};"
        : "+f"(d[0]), "+f"(d[1]), "+f"(d[2]), "+f"(d[3])
        : "r"(a0), "r"(a1), "r"(a2), "r"(a3), "r"(b0), "r"(b1));
}
__device__ __forceinline__ void cpa16(float* s, const float* g) {
    unsigned sa = (unsigned)__cvta_generic_to_shared(s);
    asm volatile("cp.async.cg.shared.global [%0], [%1], 16;" :: "r"(sa), "l"(g));
}
__device__ __forceinline__ void cp_commit() { asm volatile("cp.async.commit_group;"); }
template<int N> __device__ __forceinline__ void cp_wait() {
    asm volatile("cp.async.wait_group %0;" :: "n"(N));
}
#define GROUP_BAR(id) asm volatile("bar.sync %0, 128;" :: "r"(id) : "memory")

// ======================= rope table =======================
__global__ void rope_tab_kernel(const int* __restrict__ sp) {
    int idx = threadIdx.x;            // 1024 threads: s(4b) x pp(6b)
    int s = idx >> 6, pp = idx & 63;
    double f = (double)(sp[0] + s) * exp(-9.210340371976184 * ((double)pp / 64.0));
    double cd, sd; sincos(f, &sd, &cd);
    g_tab[idx] = make_float2((float)cd, (float)sd);
}

// ======================= GEMM 128x128, K-split =======================
#define BM 128
#define BK 32
#define AST 36
#define BST 136
#define GEMM_SMEM_BYTES ((2*BM*AST + 2*BK*BST) * 4)

__device__ void gemm_tile(const float* __restrict__ A, int lda,
                          const float* __restrict__ W, int ldw,
                          float* __restrict__ C, int ldc,
                          int m0, int n0w, int n0c, int kbase, int KT)
{
    extern __shared__ float sm[];
    float* As0 = sm;
    float* As1 = sm + BM * AST;
    float* Bs0 = sm + 2 * BM * AST;
    float* Bs1 = sm + 2 * BM * AST + BK * BST;

    int tid = threadIdx.x, lane = tid & 31, wid = tid >> 5;
    int wm = wid >> 2, wn = wid & 3;
    int gr = lane >> 2, kq = lane & 3;

    float acc[4][4][4];
#pragma unroll
    for (int mt = 0; mt < 4; mt++)
#pragma unroll
        for (int nt = 0; nt < 4; nt++)
#pragma unroll
            for (int i = 0; i < 4; i++) acc[mt][nt][i] = 0.f;

    // stage 0
    {
#pragma unroll
        for (int i = 0; i < 4; i++) {
            int idx = i * 256 + tid; int r = idx >> 3, c4 = idx & 7;
            cpa16(As0 + r * AST + c4 * 4, A + (long)(m0 + r) * lda + kbase + c4 * 4);
        }
#pragma unroll
        for (int i = 0; i < 4; i++) {
            int idx = i * 256 + tid; int r = idx >> 5, c4 = idx & 31;
            cpa16(Bs0 + r * BST + c4 * 4, W + (long)(kbase + r) * ldw + n0w + c4 * 4);
        }
        cp_commit();
    }

    for (int kt = 0; kt < KT; kt++) {
        float* Ab = (kt & 1) ? As1 : As0;
        float* Bb = (kt & 1) ? Bs1 : Bs0;
        if (kt + 1 < KT) {
            float* An = (kt & 1) ? As0 : As1;
            float* Bn = (kt & 1) ? Bs0 : Bs1;
            int k1 = kbase + (kt + 1) * BK;
#pragma unroll
            for (int i = 0; i < 4; i++) {
                int idx = i * 256 + tid; int r = idx >> 3, c4 = idx & 7;
                cpa16(An + r * AST + c4 * 4, A + (long)(m0 + r) * lda + k1 + c4 * 4);
            }
#pragma unroll
            for (int i = 0; i < 4; i++) {
                int idx = i * 256 + tid; int r = idx >> 5, c4 = idx & 31;
                cpa16(Bn + r * BST + c4 * 4, W + (long)(k1 + r) * ldw + n0w + c4 * 4);
            }
            cp_commit();
            cp_wait<1>();
        } else {
            cp_wait<0>();
        }
        __syncthreads();
#pragma unroll
        for (int kk = 0; kk < 4; kk++) {
            unsigned af[4][4], bf[4][2];
#pragma unroll
            for (int mt = 0; mt < 4; mt++) {
                int rm = wm * 64 + mt * 16;
                const float* p0 = Ab + (rm + gr) * AST + kk * 8 + kq;
                const float* p1 = Ab + (rm + gr + 8) * AST + kk * 8 + kq;
                af[mt][0] = f2tf(p0[0]); af[mt][1] = f2tf(p1[0]);
                af[mt][2] = f2tf(p0[4]); af[mt][3] = f2tf(p1[4]);
            }
#pragma unroll
            for (int nt = 0; nt < 4; nt++) {
                int cb = wn * 32 + nt * 8 + gr;
                bf[nt][0] = f2tf(Bb[(kk * 8 + kq) * BST + cb]);
                bf[nt][1] = f2tf(Bb[(kk * 8 + kq + 4) * BST + cb]);
            }
#pragma unroll
            for (int mt = 0; mt < 4; mt++)
#pragma unroll
                for (int nt = 0; nt < 4; nt++)
                    mma8(acc[mt][nt], af[mt][0], af[mt][1], af[mt][2], af[mt][3],
                         bf[nt][0], bf[nt][1]);
        }
        __syncthreads();
    }

#pragma unroll
    for (int mt = 0; mt < 4; mt++)
#pragma unroll
        for (int nt = 0; nt < 4; nt++) {
            int row = m0 + wm * 64 + mt * 16 + gr;
            int col = n0c + wn * 32 + nt * 8 + 2 * kq;
            *(float2*)(C + (long)row * ldc + col) =
                make_float2(acc[mt][nt][0], acc[mt][nt][1]);
            *(float2*)(C + (long)(row + 8) * ldc + col) =
                make_float2(acc[mt][nt][2], acc[mt][nt][3]);
        }
}

__global__ void qkv_kernel(const float* __restrict__ x, const float* __restrict__ Wq,
                           const float* __restrict__ Wk, const float* __restrict__ Wv) {
    int y = blockIdx.y, z = blockIdx.z;
    const float* W; int ldw, n0w, n0c;
    if (y < 32)      { W = Wq; ldw = 4096; n0w = y * 128;        n0c = y * 128; }
    else if (y < 40) { W = Wk; ldw = 1024; n0w = (y - 32) * 128; n0c = 4096 + (y - 32) * 128; }
    else             { W = Wv; ldw = 1024; n0w = (y - 40) * 128; n0c = 5120 + (y - 40) * 128; }
    gemm_tile(x, 4096, W, ldw, g_p[z], NC, blockIdx.x * BM, n0w, n0c, z * 1024, 32);
}

__global__ void out_kernel(const float* __restrict__ Wo) {
    int z = blockIdx.z;
    gemm_tile(g_ctx, 4096, Wo, 4096, g_p[z], 4096,
              blockIdx.x * BM, blockIdx.y * 128, blockIdx.y * 128, z * 1024, 32);
}

// ======================= combines =======================
__global__ void qkv_combine_kernel() {
    int idx = blockIdx.x * 256 + threadIdx.x;      // 786432 pairs
    int row = idx / (NC / 2);
    int p   = idx - row * (NC / 2);
    int col = 2 * p;
    float v0 = 0.f, v1 = 0.f;
#pragma unroll
    for (int h = 0; h < KS; h++) {
        const float* src = g_p[h] + (long)row * NC + col;
        v0 += src[0]; v1 += src[1];
    }
    if (col < 4096) {
        int pp = (col & 127) >> 1;
        float2 cs = g_tab[((row & 15) << 6) + pp];
        const float qs = 0.08838834764831845f;
        float t = (v0 * cs.x - v1 * cs.y) * qs;
        v1 = (v0 * cs.y + v1 * cs.x) * qs; v0 = t;
        *(float2*)(g_q + (long)row * 4096 + col) = make_float2(v0, v1);
    } else if (col < 5120) {
        int c2 = col - 4096;
        int pp = (c2 & 127) >> 1;
        float2 cs = g_tab[((row & 15) << 6) + pp];
        float t = v0 * cs.x - v1 * cs.y;
        v1 = v0 * cs.y + v1 * cs.x; v0 = t;
        *(float2*)(g_kn + (long)row * 1024 + c2) = make_float2(v0, v1);
    } else {
        *(float2*)(g_vn + (long)row * 1024 + (col - 5120)) = make_float2(v0, v1);
    }
}

__global__ void out_combine_kernel(float* __restrict__ out) {
    int idx = blockIdx.x * 256 + threadIdx.x;      // 262144 float4s
    float4 a = *(const float4*)(g_p[0] + 4 * (long)idx);
    float4 b = *(const float4*)(g_p[1] + 4 * (long)idx);
    float4 c = *(const float4*)(g_p[2] + 4 * (long)idx);
    float4 d = *(const float4*)(g_p[3] + 4 * (long)idx);
    *(float4*)(out + 4 * (long)idx) =
        make_float4(a.x + b.x + c.x + d.x, a.y + b.y + c.y + d.y,
                    a.z + b.z + c.z + d.z, a.w + b.w + c.w + d.w);
}

// ======================= attention (512 threads) =======================
#define TC   64
#define KSTR 132
#define VSTR 136
#define PST  68
#define AOFF_K0  0
#define AOFF_K1  (64*KSTR)
#define AOFF_V0  (2*64*KSTR)
#define AOFF_V1  (AOFF_V0 + 64*VSTR)
#define AOFF_P   (AOFF_V1 + 64*VSTR)
#define AOFF_EX  (AOFF_P + 64*PST)
#define ATTN_SMEM_BYTES ((AOFF_EX + 512) * 4)

__device__ __forceinline__ void attn_load_kv(
    const float* __restrict__ cache_k, const float* __restrict__ cache_v,
    int b, int kvh, int start, int kvlen, int t0, float* Ks, float* Vs, int tid)
{
#pragma unroll
    for (int i = 0; i < 4; i++) {
        int idx = i * 512 + tid; int r = idx >> 5, c4 = idx & 31;
        int t = t0 + r;
        if (t < start) {
            long o = ((((long)b * MAXS_ + t) * KVH_) + kvh) * HD_ + c4 * 4;
            cpa16(Ks + r * KSTR + c4 * 4, cache_k + o);
            cpa16(Vs + r * VSTR + c4 * 4, cache_v + o);
        } else if (t < kvlen) {
            long o = (((long)(b * S_ + (t - start))) * KVH_ + kvh) * HD_ + c4 * 4;
            cpa16(Ks + r * KSTR + c4 * 4, g_kn + o);
            cpa16(Vs + r * VSTR + c4 * 4, g_vn + o);
        } else {
            *(float4*)(Ks + r * KSTR + c4 * 4) = make_float4(0.f, 0.f, 0.f, 0.f);
            *(float4*)(Vs + r * VSTR + c4 * 4) = make_float4(0.f, 0.f, 0.f, 0.f);
        }
    }
    cp_commit();
}

__global__ void __launch_bounds__(512, 1)
attn_kernel(const float* __restrict__ cache_k,
            const float* __restrict__ cache_v,
            const int* __restrict__ sp)
{
    extern __shared__ float sm[];
    float* Ksb[2] = { sm + AOFF_K0, sm + AOFF_K1 };
    float* Vsb[2] = { sm + AOFF_V0, sm + AOFF_V1 };
    float* Ps = sm + AOFF_P;
    float* ex = sm + AOFF_EX;  // [0:256) m partials (wn major), [256:512) l partials

    int tid = threadIdx.x, lane = tid & 31, wid = tid >> 5;
    int b = blockIdx.x >> 3, kvh = blockIdx.x & 7;
    int start = sp[0], kvlen = start + S_;
    int wm = wid & 3, wn = wid >> 2;      // 4 m-groups x 4 n-groups
    int gr = lane >> 2, kq = lane & 3;
    int rm = wm * 16;

    // Q fragments resident in registers for all chunks
    unsigned qa[16][4];
    {
        int r0 = rm + gr, r1 = r0 + 8;
        const float* q0 = g_q + (long)(b * S_ + (r0 & 15)) * D_ + (kvh * NREP_ + (r0 >> 4)) * HD_;
        const float* q1 = g_q + (long)(b * S_ + (r1 & 15)) * D_ + (kvh * NREP_ + (r1 >> 4)) * HD_;
#pragma unroll
        for (int kk = 0; kk < 16; kk++) {
            qa[kk][0] = f2tf(q0[kk * 8 + kq]);
            qa[kk][1] = f2tf(q1[kk * 8 + kq]);
            qa[kk][2] = f2tf(q0[kk * 8 + kq + 4]);
            qa[kk][3] = f2tf(q1[kk * 8 + kq + 4]);
        }
    }

    float m0r = -1e30f, m1r = -1e30f, l0r = 0.f, l1r = 0.f;
    float cacc[4][4];
#pragma unroll
    for (int nt = 0; nt < 4; nt++)
#pragma unroll
        for (int i = 0; i < 4; i++) cacc[nt][i] = 0.f;

    int NCH = (kvlen + TC - 1) / TC;
    attn_load_kv(cache_k, cache_v, b, kvh, start, kvlen, 0, Ksb[0], Vsb[0], tid);
    attn_load_kv(cache_k, cache_v, b, kvh, start, kvlen, TC, Ksb[1], Vsb[1], tid);
    cp_wait<1>();
    __syncthreads();

    for (int j = 0; j < NCH; j++) {
        const float* Kb = Ksb[j & 1];
        const float* Vb = Vsb[j & 1];

        // ---- S = Q K^T : this warp covers cols [wn*16, wn*16+16) ----
        float sacc[2][4];
#pragma unroll
        for (int nt = 0; nt < 2; nt++)
#pragma unroll
            for (int i = 0; i < 4; i++) sacc[nt][i] = 0.f;
#pragma unroll
        for (int kk = 0; kk < 16; kk++) {
#pragma unroll
            for (int nt = 0; nt < 2; nt++) {
                int cb = wn * 16 + nt * 8 + gr;
                unsigned b0 = f2tf(Kb[cb * KSTR + kk * 8 + kq]);
                unsigned b1 = f2tf(Kb[cb * KSTR + kk * 8 + kq + 4]);
                mma8(sacc[nt], qa[kk][0], qa[kk][1], qa[kk][2], qa[kk][3], b0, b1);
            }
        }

        if (j == NCH - 1 && (kvlen & (TC - 1))) {
#pragma unroll
            for (int nt = 0; nt < 2; nt++) {
                int cb = j * TC + wn * 16 + nt * 8 + 2 * kq;
                if (cb >= kvlen)     { sacc[nt][0] = -1e30f; sacc[nt][2] = -1e30f; }
                if (cb + 1 >= kvlen) { sacc[nt][1] = -1e30f; sacc[nt][3] = -1e30f; }
            }
        }

        // ---- online softmax across 4 wn warps ----
        float mw0 = fmaxf(fmaxf(sacc[0][0], sacc[0][1]), fmaxf(sacc[1][0], sacc[1][1]));
        float mw1 = fmaxf(fmaxf(sacc[0][2], sacc[0][3]), fmaxf(sacc[1][2], sacc[1][3]));
        mw0 = fmaxf(mw0, __shfl_xor_sync(0xffffffffu, mw0, 1));
        mw0 = fmaxf(mw0, __shfl_xor_sync(0xffffffffu, mw0, 2));
        mw1 = fmaxf(mw1, __shfl_xor_sync(0xffffffffu, mw1, 1));
        mw1 = fmaxf(mw1, __shfl_xor_sync(0xffffffffu, mw1, 2));
        if (kq == 0) { ex[wn * 64 + rm + gr] = mw0; ex[wn * 64 + rm + gr + 8] = mw1; }
        GROUP_BAR(1 + wm);
        float M0 = m0r, M1 = m1r;
#pragma unroll
        for (int w = 0; w < 4; w++) {
            M0 = fmaxf(M0, ex[w * 64 + rm + gr]);
            M1 = fmaxf(M1, ex[w * 64 + rm + gr + 8]);
        }

        float l0l = 0.f, l1l = 0.f;
#pragma unroll
        for (int nt = 0; nt < 2; nt++) {
            sacc[nt][0] = __expf(sacc[nt][0] - M0);
            sacc[nt][1] = __expf(sacc[nt][1] - M0);
            sacc[nt][2] = __expf(sacc[nt][2] - M1);
            sacc[nt][3] = __expf(sacc[nt][3] - M1);
            l0l += sacc[nt][0] + sacc[nt][1];
            l1l += sacc[nt][2] + sacc[nt][3];
        }
        l0l += __shfl_xor_sync(0xffffffffu, l0l, 1);
        l0l += __shfl_xor_sync(0xffffffffu, l0l, 2);
        l1l += __shfl_xor_sync(0xffffffffu, l1l, 1);
        l1l += __shfl_xor_sync(0xffffffffu, l1l, 2);
        if (kq == 0) { ex[256 + wn * 64 + rm + gr] = l0l; ex[256 + wn * 64 + rm + gr + 8] = l1l; }

        // store P (pre-converted to tf32 bits) while l partials propagate
#pragma unroll
        for (int nt = 0; nt < 2; nt++) {
            int cb = wn * 16 + nt * 8 + 2 * kq;
            *(float2*)&Ps[(rm + gr) * PST + cb] =
                make_float2(__uint_as_float(f2tf(sacc[nt][0])),
                            __uint_as_float(f2tf(sacc[nt][1])));
            *(float2*)&Ps[(rm + gr + 8) * PST + cb] =
                make_float2(__uint_as_float(f2tf(sacc[nt][2])),
                            __uint_as_float(f2tf(sacc[nt][3])));
        }
        GROUP_BAR(1 + wm);    // l partials + full P row-group visible

        float L0 = 0.f, L1 = 0.f;
#pragma unroll
        for (int w = 0; w < 4; w++) {
            L0 += ex[256 + w * 64 + rm + gr];
            L1 += ex[256 + w * 64 + rm + gr + 8];
        }
        float sc0 = __expf(m0r - M0), sc1 = __expf(m1r - M1);
        l0r = l0r * sc0 + L0;  l1r = l1r * sc1 + L1;
        m0r = M0;  m1r = M1;
#pragma unroll
        for (int nt = 0; nt < 4; nt++) {
            cacc[nt][0] *= sc0; cacc[nt][1] *= sc0;
            cacc[nt][2] *= sc1; cacc[nt][3] *= sc1;
        }

        // ---- O += P V : this warp covers dims [wn*32, wn*32+32) ----
#pragma unroll
        for (int kk = 0; kk < 8; kk++) {
            unsigned a0 = __float_as_uint(Ps[(rm + gr) * PST + kk * 8 + kq]);
            unsigned a1 = __float_as_uint(Ps[(rm + gr + 8) * PST + kk * 8 + kq]);
            unsigned a2 = __float_as_uint(Ps[(rm + gr) * PST + kk * 8 + kq + 4]);
            unsigned a3 = __float_as_uint(Ps[(rm + gr + 8) * PST + kk * 8 + kq + 4]);
#pragma unroll
            for (int nt = 0; nt < 4; nt++) {
                int dc = wn * 32 + nt * 8 + gr;
                unsigned b0 = f2tf(Vb[(kk * 8 + kq) * VSTR + dc]);
                unsigned b1 = f2tf(Vb[(kk * 8 + kq + 4) * VSTR + dc]);
                mma8(cacc[nt], a0, a1, a2, a3, b0, b1);
            }
        }

        cp_wait<0>();      // chunk j+1 resident
        __syncthreads();   // PV(j) done everywhere; safe to refill buffer j
        if (j + 2 < NCH)
            attn_load_kv(cache_k, cache_v, b, kvh, start, kvlen,
                         (j + 2) * TC, Ksb[j & 1], Vsb[j & 1], tid);
    }

    // ---- epilogue ----
    float inv0 = 1.f / l0r, inv1 = 1.f / l1r;
    int r0 = rm + gr, r1 = r0 + 8;
    long base0 = (long)(b * S_ + (r0 & 15)) * D_ + (kvh * NREP_ + (r0 >> 4)) * HD_;
    long base1 = (long)(b * S_ + (r1 & 15)) * D_ + (kvh * NREP_ + (r1 >> 4)) * HD_;
#pragma unroll
    for (int nt = 0; nt < 4; nt++) {
        int col = wn * 32 + nt * 8 + 2 * kq;
        *(float2*)(g_ctx + base0 + col) = make_float2(cacc[nt][0] * inv0, cacc[nt][1] * inv0);
        *(float2*)(g_ctx + base1 + col) = make_float2(cacc[nt][2] * inv1, cacc[nt][3] * inv1);
    }
}

// ======================= launch =======================
extern "C" void kernel_launch(void* const* d_in, const int* in_sizes, int n_in,
                              void* d_out, int out_size) {
    const float* x       = (const float*)d_in[0];
    const float* Wq      = (const float*)d_in[1];
    const float* Wk      = (const float*)d_in[2];
    const float* Wv      = (const float*)d_in[3];
    const float* Wo      = (const float*)d_in[4];
    const float* cache_k = (const float*)d_in[5];
    const float* cache_v = (const float*)d_in[6];
    const int*   sp      = (const int*)d_in[7];
    float* out = (float*)d_out;

    cudaFuncSetAttribute(qkv_kernel,  cudaFuncAttributeMaxDynamicSharedMemorySize, GEMM_SMEM_BYTES);
    cudaFuncSetAttribute(out_kernel,  cudaFuncAttributeMaxDynamicSharedMemorySize, GEMM_SMEM_BYTES);
    cudaFuncSetAttribute(attn_kernel, cudaFuncAttributeMaxDynamicSharedMemorySize, ATTN_SMEM_BYTES);

    rope_tab_kernel<<<1, 1024>>>(sp);
    qkv_kernel<<<dim3(2, 48, KS), 256, GEMM_SMEM_BYTES>>>(x, Wq, Wk, Wv);
    qkv_combine_kernel<<<(MROWS * NC / 2) / 256, 256>>>();
    attn_kernel<<<128, 512, ATTN_SMEM_BYTES>>>(cache_k, cache_v, sp);
    out_kernel<<<dim3(2, 32, KS), 256, GEMM_SMEM_BYTES>>>(Wo);
    out_combine_kernel<<<(MROWS * D_ / 4) / 256, 256>>>(out);
}